// round 1
// baseline (speedup 1.0000x reference)
#include <cuda_runtime.h>
#include <math.h>

#define NPTS 1024
#define EMB  128
#define HID  128
#define TI   16
#define TJ   8
#define MB   128   // TI*TJ pairs per block
#define NB   128   // g-dim per block (= HID)

// Device-global scratch (no allocations allowed in kernel_launch)
__device__ float g_A[NPTS * HID];     // A[j][h] = z1[j] . W1[:, :128][h]
__device__ float g_B[NPTS * HID];     // B[i][h] = z2[i] . W1[:, 128:][h] + b1[h]
__device__ float g_W2T[HID * HID];    // W2T[h][g] = W2[g][h]

__device__ __forceinline__ float gelu_exact(float x) {
    return 0.5f * x * (1.0f + erff(x * 0.70710678118654752f));
}

// ---------------------------------------------------------------------------
// Precompute: blocks [0,1024) -> A rows, [1024,2048) -> B rows,
//             blocks [2048,2176) -> W2 transpose rows.
// ---------------------------------------------------------------------------
__global__ void precompute_kernel(const float* __restrict__ z1,
                                  const float* __restrict__ z2,
                                  const float* __restrict__ W1,
                                  const float* __restrict__ b1,
                                  const float* __restrict__ W2) {
    int row = blockIdx.x;
    int h = threadIdx.x;  // 128 threads

    if (row < 2 * NPTS) {
        __shared__ float zsh[EMB];
        const float* z = (row < NPTS) ? (z1 + (size_t)row * EMB)
                                      : (z2 + (size_t)(row - NPTS) * EMB);
        zsh[h] = z[h];
        __syncthreads();
        const float* w = (row < NPTS) ? (W1 + (size_t)h * (2 * EMB))
                                      : (W1 + (size_t)h * (2 * EMB) + EMB);
        float s = 0.f;
#pragma unroll 8
        for (int d = 0; d < EMB; ++d) s += zsh[d] * w[d];
        if (row < NPTS) g_A[(size_t)row * HID + h] = s;
        else            g_B[(size_t)(row - NPTS) * HID + h] = s + b1[h];
    } else {
        int g = row - 2 * NPTS;  // 0..127
        g_W2T[(size_t)h * HID + g] = W2[(size_t)g * HID + h];
    }
}

// ---------------------------------------------------------------------------
// Main fused kernel: one block = 16 (i) x 8 (j) pairs = 128 "rows",
// full 128-wide hidden layer. 256 threads, 8x8 micro-tiles.
// ---------------------------------------------------------------------------
struct SmemMain {
    float sH[128][128];   // sH[h][m] = gelu(A[j_m][h] + B[i_m][h])   (k-major)
    float sW[128][128];   // sW[h][g] = W2[g][h]                       (k-major)
    float sA[TJ][132];    // padded to avoid bank conflicts in fill
    float sB[TI][132];
    float sb2[128];
    float sw3[128];
    float sRed[128][17];  // partial sums: [m][tn]
};

__global__ __launch_bounds__(256, 1)
void pair_mlp_kernel(const float* __restrict__ b2,
                     const float* __restrict__ W3,
                     const float* __restrict__ b3,
                     float* __restrict__ out) {
    extern __shared__ char smem_raw[];
    SmemMain& sm = *reinterpret_cast<SmemMain*>(smem_raw);

    const int tid = threadIdx.x;
    const int j0 = blockIdx.x * TJ;
    const int i0 = blockIdx.y * TI;

    // ---- Stage operands into SMEM ----
    {
        const float4* w4 = reinterpret_cast<const float4*>(g_W2T);
        float4* sW4 = reinterpret_cast<float4*>(&sm.sW[0][0]);
        for (int k = tid; k < 128 * 32; k += 256) sW4[k] = w4[k];
    }
    for (int k = tid; k < TJ * HID; k += 256) {
        int j = k >> 7, h = k & 127;
        sm.sA[j][h] = g_A[(size_t)(j0 + j) * HID + h];
    }
    for (int k = tid; k < TI * HID; k += 256) {
        int i = k >> 7, h = k & 127;
        sm.sB[i][h] = g_B[(size_t)(i0 + i) * HID + h];
    }
    if (tid < 128) { sm.sb2[tid] = b2[tid]; sm.sw3[tid] = W3[tid]; }
    __syncthreads();

    // ---- Fill h1 tile: sH[h][m] = gelu(A[j][h] + B[i][h]) ----
    for (int idx = tid; idx < 128 * 128; idx += 256) {
        int h = idx >> 7, m = idx & 127;
        float x = sm.sA[m & 7][h] + sm.sB[m >> 3][h];
        sm.sH[h][m] = gelu_exact(x);
    }
    __syncthreads();

    // ---- 128x128x128 register GEMM: acc[r][c] = sum_h h1[m_r][h]*W2[n_c][h] ----
    const int tm = tid & 15;   // 16 threads over m
    const int tn = tid >> 4;   // 16 threads over n

    float acc[8][8];
#pragma unroll
    for (int r = 0; r < 8; ++r)
#pragma unroll
        for (int c = 0; c < 8; ++c) acc[r][c] = 0.f;

#pragma unroll 2
    for (int h = 0; h < 128; ++h) {
        float4 a0 = *reinterpret_cast<const float4*>(&sm.sH[h][tm * 4]);
        float4 a1 = *reinterpret_cast<const float4*>(&sm.sH[h][64 + tm * 4]);
        float4 b0 = *reinterpret_cast<const float4*>(&sm.sW[h][tn * 4]);
        float4 b1v = *reinterpret_cast<const float4*>(&sm.sW[h][64 + tn * 4]);
        float am[8] = {a0.x, a0.y, a0.z, a0.w, a1.x, a1.y, a1.z, a1.w};
        float bn[8] = {b0.x, b0.y, b0.z, b0.w, b1v.x, b1v.y, b1v.z, b1v.w};
#pragma unroll
        for (int r = 0; r < 8; ++r)
#pragma unroll
            for (int c = 0; c < 8; ++c)
                acc[r][c] = fmaf(am[r], bn[c], acc[r][c]);
    }

    // ---- Epilogue: sum_c gelu(acc+b2[n]) * W3[n], reduce over tn ----
    float part[8];
#pragma unroll
    for (int r = 0; r < 8; ++r) part[r] = 0.f;

#pragma unroll
    for (int c = 0; c < 8; ++c) {
        int n = (c < 4) ? (tn * 4 + c) : (64 + tn * 4 + (c - 4));
        float bb = sm.sb2[n];
        float ww = sm.sw3[n];
#pragma unroll
        for (int r = 0; r < 8; ++r)
            part[r] += gelu_exact(acc[r][c] + bb) * ww;
    }

#pragma unroll
    for (int r = 0; r < 8; ++r) {
        int m = (r < 4) ? (tm * 4 + r) : (64 + tm * 4 + (r - 4));
        sm.sRed[m][tn] = part[r];
    }
    __syncthreads();

    if (tid < 128) {
        int m = tid;
        float s = b3[0];
#pragma unroll
        for (int k = 0; k < 16; ++k) s += sm.sRed[m][k];
        int i = i0 + (m >> 3);
        int j = j0 + (m & 7);
        out[(size_t)i * NPTS + j] = s;
    }
}

// ---------------------------------------------------------------------------
extern "C" void kernel_launch(void* const* d_in, const int* in_sizes, int n_in,
                              void* d_out, int out_size) {
    const float* z1 = (const float*)d_in[0];
    const float* z2 = (const float*)d_in[1];
    const float* W1 = (const float*)d_in[2];
    const float* b1 = (const float*)d_in[3];
    const float* W2 = (const float*)d_in[4];
    const float* b2 = (const float*)d_in[5];
    const float* W3 = (const float*)d_in[6];
    const float* b3 = (const float*)d_in[7];
    float* out = (float*)d_out;

    (void)in_sizes; (void)n_in; (void)out_size;

    // Stage 1: A, B (with b1 folded) and W2 transpose.
    precompute_kernel<<<2 * NPTS + HID, 128>>>(z1, z2, W1, b1, W2);

    // Stage 2: fused pairwise MLP.
    static const size_t smem_bytes = sizeof(SmemMain);
    cudaFuncSetAttribute(pair_mlp_kernel,
                         cudaFuncAttributeMaxDynamicSharedMemorySize,
                         (int)smem_bytes);
    dim3 grid(NPTS / TJ, NPTS / TI);  // 128 x 64 = 8192 blocks
    pair_mlp_kernel<<<grid, 256, smem_bytes>>>(b2, W3, b3, out);
}

// round 3
// speedup vs baseline: 2.1657x; 2.1657x over previous
#include <cuda_runtime.h>
#include <cuda_bf16.h>
#include <math.h>
#include <stdint.h>

#define NPTS 1024
#define EMB  128
#define HID  128
#define TI   16
#define TJ   8
#define NTILES ((NPTS/TI) * (NPTS/TJ))   // 64 * 128 = 8192
#define THREADS 512

// ---------------------------------------------------------------------------
// Device-global scratch
// ---------------------------------------------------------------------------
__device__ float g_A[NPTS * HID];               // A[j][h] = z1[j].W1a[h]
__device__ float g_B[NPTS * HID];               // B[i][h] = z2[i].W1b[h] + b1[h]
__device__ unsigned short g_W2hi[HID * HID];    // bf16 hi, swizzled [n][k] layout
__device__ unsigned short g_W2lo[HID * HID];    // bf16 lo, swizzled [n][k] layout

__device__ __forceinline__ float gelu_exact(float x) {
    return 0.5f * x * (1.0f + erff(x * 0.70710678118654752f));
}

__device__ __forceinline__ uint32_t smem_u32(const void* p) {
    uint32_t a;
    asm("{ .reg .u64 t; cvta.to.shared.u64 t, %1; cvt.u32.u64 %0, t; }" : "=r"(a) : "l"(p));
    return a;
}

// ldmatrix x4 (baseline PTX, sm_75+)
#define LDSM_X4(r0, r1, r2, r3, addr) \
    asm volatile("ldmatrix.sync.aligned.m8n8.x4.shared.b16 {%0,%1,%2,%3}, [%4];" \
                 : "=r"(r0), "=r"(r1), "=r"(r2), "=r"(r3) : "r"(addr))

// mma.sync m16n8k16 bf16 -> f32 (baseline PTX, sm_80+)
#define MMA_16816(c, a, b0, b1) \
    asm volatile("mma.sync.aligned.m16n8k16.row.col.f32.bf16.bf16.f32 " \
                 "{%0,%1,%2,%3}, {%4,%5,%6,%7}, {%8,%9}, {%0,%1,%2,%3};" \
                 : "+f"((c)[0]), "+f"((c)[1]), "+f"((c)[2]), "+f"((c)[3]) \
                 : "r"((a)[0]), "r"((a)[1]), "r"((a)[2]), "r"((a)[3]), \
                   "r"(b0), "r"(b1))

// Swizzled byte offset inside a 128x128-bf16 operand array:
//   row-major, 256 B/row, 16B chunks XOR-swizzled by (row & 7).
__device__ __forceinline__ uint32_t sw_off(int row, int kbyte) {
    int c = kbyte >> 4;
    return (uint32_t)(row * 256 + (((c ^ (row & 7)) << 4) | (kbyte & 15)));
}

// ---------------------------------------------------------------------------
// Stage 1: A, B (b1 folded), W2 -> bf16 hi/lo in swizzled [n][k] layout
// ---------------------------------------------------------------------------
__global__ void precompute_kernel(const float* __restrict__ z1,
                                  const float* __restrict__ z2,
                                  const float* __restrict__ W1,
                                  const float* __restrict__ b1,
                                  const float* __restrict__ W2) {
    int row = blockIdx.x;
    int h = threadIdx.x;  // 128 threads
    if (row < 2 * NPTS) {
        __shared__ float zsh[EMB];
        const float* z = (row < NPTS) ? (z1 + (size_t)row * EMB)
                                      : (z2 + (size_t)(row - NPTS) * EMB);
        zsh[h] = z[h];
        __syncthreads();
        const float* w = (row < NPTS) ? (W1 + (size_t)h * (2 * EMB))
                                      : (W1 + (size_t)h * (2 * EMB) + EMB);
        float s = 0.f;
#pragma unroll 8
        for (int d = 0; d < EMB; ++d) s += zsh[d] * w[d];
        if (row < NPTS) g_A[(size_t)row * HID + h] = s;
        else            g_B[(size_t)(row - NPTS) * HID + h] = s + b1[h];
    } else {
        int g = row - 2 * NPTS;   // n index 0..127
        float w = W2[(size_t)g * HID + h];
        __nv_bfloat16 hi = __float2bfloat16(w);
        __nv_bfloat16 lo = __float2bfloat16(w - __bfloat162float(hi));
        uint32_t off = sw_off(g, 2 * h) >> 1;   // ushort index
        g_W2hi[off] = __bfloat16_as_ushort(hi);
        g_W2lo[off] = __bfloat16_as_ushort(lo);
    }
}

// ---------------------------------------------------------------------------
// SMEM layout (byte offsets)
// ---------------------------------------------------------------------------
#define OFF_HHI 0
#define OFF_HLO 32768
#define OFF_WHI 65536
#define OFF_WLO 98304
#define OFF_A   131072                 // 8*128 floats  (4 KB)
#define OFF_B   (OFF_A + 4096)        // 16*128 floats (8 KB)
#define OFF_B2  (OFF_B + 8192)        // 128 floats
#define OFF_W3  (OFF_B2 + 512)        // 128 floats
#define OFF_RED (OFF_W3 + 512)        // 128*5 floats
#define SMEM_TOTAL (OFF_RED + 128 * 5 * 4 + 128)

// ---------------------------------------------------------------------------
// Persistent fused kernel
// ---------------------------------------------------------------------------
__global__ __launch_bounds__(THREADS, 1)
void pair_mlp_mma(const float* __restrict__ b2,
                  const float* __restrict__ W3,
                  const float* __restrict__ b3,
                  float* __restrict__ out) {
    extern __shared__ char smem[];
    const uint32_t sb = smem_u32(smem);
    const int tid  = threadIdx.x;
    const int wid  = tid >> 5;
    const int lane = tid & 31;

    float* sA   = reinterpret_cast<float*>(smem + OFF_A);
    float* sB   = reinterpret_cast<float*>(smem + OFF_B);
    float* sb2  = reinterpret_cast<float*>(smem + OFF_B2);
    float* sw3  = reinterpret_cast<float*>(smem + OFF_W3);
    float* sRed = reinterpret_cast<float*>(smem + OFF_RED);

    // ---- one-time: stage W2 hi/lo (pre-swizzled -> flat copy), b2, w3 ----
    {
        const uint4* shi = reinterpret_cast<const uint4*>(g_W2hi);
        const uint4* slo = reinterpret_cast<const uint4*>(g_W2lo);
        uint4* dh = reinterpret_cast<uint4*>(smem + OFF_WHI);
        uint4* dl = reinterpret_cast<uint4*>(smem + OFF_WLO);
        for (int k = tid; k < 2048; k += THREADS) { dh[k] = shi[k]; dl[k] = slo[k]; }
        if (tid < 128) { sb2[tid] = b2[tid]; sw3[tid] = W3[tid]; }
    }
    const float b3v = b3[0];

    // ---- warp geometry ----
    const int wm = wid & 3;            // m-tile of warp (4)
    const int wn = wid >> 2;           // n-tile of warp (4)
    const int Mbase = wm * 32;
    const int Nbase = wn * 32;

    // A ldmatrix lane geometry
    const int arow0 = Mbase + (lane & 15);     // row for mt=0
    const int aKhi  = (lane >> 4);             // 0/1 : +8 k elements
    const int fA    = arow0 & 7;
    // B ldmatrix lane geometry
    const int bn0   = Nbase + ((lane >> 4) << 3) + (lane & 7);
    const int bKhi  = (lane >> 3) & 1;         // 0/1 : +8 k elements
    const int fB    = bn0 & 7;

    __syncthreads();

    for (int t = blockIdx.x; t < NTILES; t += gridDim.x) {
        const int j0 = (t & 127) * TJ;
        const int i0 = (t >> 7) * TI;

        // ---- stage A (8x128) and B (16x128) rows ----
        {
            const float4* ga = reinterpret_cast<const float4*>(g_A + (size_t)j0 * HID);
            const float4* gb = reinterpret_cast<const float4*>(g_B + (size_t)i0 * HID);
            float4* da = reinterpret_cast<float4*>(sA);
            float4* db = reinterpret_cast<float4*>(sB);
            if (tid < 256) da[tid] = ga[tid];
            db[tid] = gb[tid];                       // 512 float4
        }
        __syncthreads();

        // ---- fill h1 = gelu(A+B) as bf16 hi/lo, swizzled [m][k] ----
        {
            const int rb = wid * 8;
#pragma unroll
            for (int r = 0; r < 8; ++r) {
                const int m  = rb + r;
                const int jj = m & 7;
                const int ii = m >> 3;
                float2 av0 = *reinterpret_cast<const float2*>(sA + jj * 128 + 2 * lane);
                float2 av1 = *reinterpret_cast<const float2*>(sA + jj * 128 + 64 + 2 * lane);
                float2 bv0 = *reinterpret_cast<const float2*>(sB + ii * 128 + 2 * lane);
                float2 bv1 = *reinterpret_cast<const float2*>(sB + ii * 128 + 64 + 2 * lane);
                float y00 = gelu_exact(av0.x + bv0.x);
                float y01 = gelu_exact(av0.y + bv0.y);
                float y10 = gelu_exact(av1.x + bv1.x);
                float y11 = gelu_exact(av1.y + bv1.y);
                __nv_bfloat16 h00 = __float2bfloat16(y00);
                __nv_bfloat16 h01 = __float2bfloat16(y01);
                __nv_bfloat16 h10 = __float2bfloat16(y10);
                __nv_bfloat16 h11 = __float2bfloat16(y11);
                __nv_bfloat16 l00 = __float2bfloat16(y00 - __bfloat162float(h00));
                __nv_bfloat16 l01 = __float2bfloat16(y01 - __bfloat162float(h01));
                __nv_bfloat16 l10 = __float2bfloat16(y10 - __bfloat162float(h10));
                __nv_bfloat16 l11 = __float2bfloat16(y11 - __bfloat162float(h11));
                uint32_t hp0 = ((uint32_t)__bfloat16_as_ushort(h01) << 16) | __bfloat16_as_ushort(h00);
                uint32_t hp1 = ((uint32_t)__bfloat16_as_ushort(h11) << 16) | __bfloat16_as_ushort(h10);
                uint32_t lp0 = ((uint32_t)__bfloat16_as_ushort(l01) << 16) | __bfloat16_as_ushort(l00);
                uint32_t lp1 = ((uint32_t)__bfloat16_as_ushort(l11) << 16) | __bfloat16_as_ushort(l10);
                const uint32_t o0 = sw_off(m, 4 * lane);        // k = 2*lane
                const uint32_t o1 = sw_off(m, 128 + 4 * lane);  // k = 64+2*lane
                *reinterpret_cast<uint32_t*>(smem + OFF_HHI + o0) = hp0;
                *reinterpret_cast<uint32_t*>(smem + OFF_HHI + o1) = hp1;
                *reinterpret_cast<uint32_t*>(smem + OFF_HLO + o0) = lp0;
                *reinterpret_cast<uint32_t*>(smem + OFF_HLO + o1) = lp1;
            }
        }
        __syncthreads();

        // ---- mainloop: 3-pass split-bf16 MMA ----
        float acc[2][4][4];
#pragma unroll
        for (int mt = 0; mt < 2; ++mt)
#pragma unroll
            for (int nt = 0; nt < 4; ++nt)
#pragma unroll
                for (int ri = 0; ri < 4; ++ri) acc[mt][nt][ri] = 0.f;

#pragma unroll
        for (int ks = 0; ks < 8; ++ks) {
            uint32_t ahi[2][4], alo[2][4], bhi[2][4], blo[2][4];
            const int cA = 2 * ks + aKhi;
            const int cB = 2 * ks + bKhi;
#pragma unroll
            for (int mt = 0; mt < 2; ++mt) {
                const uint32_t offA = (uint32_t)((arow0 + mt * 16) * 256 + (((cA ^ fA) << 4)));
                LDSM_X4(ahi[mt][0], ahi[mt][1], ahi[mt][2], ahi[mt][3], sb + OFF_HHI + offA);
                LDSM_X4(alo[mt][0], alo[mt][1], alo[mt][2], alo[mt][3], sb + OFF_HLO + offA);
            }
#pragma unroll
            for (int np = 0; np < 2; ++np) {
                const uint32_t offB = (uint32_t)((bn0 + np * 16) * 256 + (((cB ^ fB) << 4)));
                LDSM_X4(bhi[np][0], bhi[np][1], bhi[np][2], bhi[np][3], sb + OFF_WHI + offB);
                LDSM_X4(blo[np][0], blo[np][1], blo[np][2], blo[np][3], sb + OFF_WLO + offB);
            }
#pragma unroll
            for (int mt = 0; mt < 2; ++mt)
#pragma unroll
                for (int nt = 0; nt < 4; ++nt) {
                    const int np = nt >> 1;
                    const int o  = (nt & 1) * 2;
                    MMA_16816(acc[mt][nt], ahi[mt], bhi[np][o], bhi[np][o + 1]);
                    MMA_16816(acc[mt][nt], ahi[mt], blo[np][o], blo[np][o + 1]);
                    MMA_16816(acc[mt][nt], alo[mt], bhi[np][o], bhi[np][o + 1]);
                }
        }

        // ---- epilogue: gelu(acc+b2)*w3, reduce over n ----
        float part[2][2] = {{0.f, 0.f}, {0.f, 0.f}};
#pragma unroll
        for (int mt = 0; mt < 2; ++mt)
#pragma unroll
            for (int nt = 0; nt < 4; ++nt)
#pragma unroll
                for (int ri = 0; ri < 4; ++ri) {
                    const int n = Nbase + nt * 8 + ((lane & 3) << 1) + (ri & 1);
                    const float x = acc[mt][nt][ri] + sb2[n];
                    part[mt][ri >> 1] += gelu_exact(x) * sw3[n];
                }
#pragma unroll
        for (int mt = 0; mt < 2; ++mt)
#pragma unroll
            for (int hh = 0; hh < 2; ++hh) {
                float v = part[mt][hh];
                v += __shfl_xor_sync(0xFFFFFFFFu, v, 1);
                v += __shfl_xor_sync(0xFFFFFFFFu, v, 2);
                part[mt][hh] = v;
            }
        if ((lane & 3) == 0) {
            const int g = lane >> 2;
#pragma unroll
            for (int mt = 0; mt < 2; ++mt)
#pragma unroll
                for (int hh = 0; hh < 2; ++hh) {
                    const int m = Mbase + mt * 16 + hh * 8 + g;
                    sRed[m * 5 + wn] = part[mt][hh];
                }
        }
        __syncthreads();

        if (tid < 128) {
            const float s = b3v + sRed[tid * 5 + 0] + sRed[tid * 5 + 1]
                                + sRed[tid * 5 + 2] + sRed[tid * 5 + 3];
            const int oi = i0 + (tid >> 3);
            const int oj = j0 + (tid & 7);
            out[(size_t)oi * NPTS + oj] = s;
        }
        // next iteration's first __syncthreads (after staging) guards reuse
    }
}

// ---------------------------------------------------------------------------
extern "C" void kernel_launch(void* const* d_in, const int* in_sizes, int n_in,
                              void* d_out, int out_size) {
    const float* z1 = (const float*)d_in[0];
    const float* z2 = (const float*)d_in[1];
    const float* W1 = (const float*)d_in[2];
    const float* b1 = (const float*)d_in[3];
    const float* W2 = (const float*)d_in[4];
    const float* b2 = (const float*)d_in[5];
    const float* W3 = (const float*)d_in[6];
    const float* b3 = (const float*)d_in[7];
    float* out = (float*)d_out;
    (void)in_sizes; (void)n_in; (void)out_size;

    precompute_kernel<<<2 * NPTS + HID, 128>>>(z1, z2, W1, b1, W2);

    int sm_count = 0;
    cudaDeviceGetAttribute(&sm_count, cudaDevAttrMultiProcessorCount, 0);
    cudaFuncSetAttribute(pair_mlp_mma,
                         cudaFuncAttributeMaxDynamicSharedMemorySize, SMEM_TOTAL);
    pair_mlp_mma<<<sm_count, THREADS, SMEM_TOTAL>>>(b2, W3, b3, out);
}

// round 4
// speedup vs baseline: 2.2326x; 1.0309x over previous
#include <cuda_runtime.h>
#include <cuda_bf16.h>
#include <math.h>
#include <stdint.h>

#define NPTS 1024
#define EMB  128
#define HID  128
#define TI   8
#define TJ   8
#define NTILES ((NPTS/TI) * (NPTS/TJ))   // 128 * 128 = 16384
#define THREADS 512
#define NBUF 4

// ---------------------------------------------------------------------------
// Device-global scratch
// ---------------------------------------------------------------------------
__device__ float g_A[NPTS * HID];               // A[j][h] = z1[j].W1a[h]
__device__ float g_B[NPTS * HID];               // B[i][h] = z2[i].W1b[h] + b1[h]
__device__ unsigned short g_W2hi[HID * HID];    // bf16 hi, swizzled [n][k]
__device__ unsigned short g_W2lo[HID * HID];    // bf16 lo, swizzled [n][k]

__device__ __forceinline__ float gelu_exact(float x) {
    return 0.5f * x * (1.0f + erff(x * 0.70710678118654752f));
}

__device__ __forceinline__ uint32_t smem_u32(const void* p) {
    uint32_t a;
    asm("{ .reg .u64 t; cvta.to.shared.u64 t, %1; cvt.u32.u64 %0, t; }" : "=r"(a) : "l"(p));
    return a;
}

#define LDSM_X4(r0, r1, r2, r3, addr) \
    asm volatile("ldmatrix.sync.aligned.m8n8.x4.shared.b16 {%0,%1,%2,%3}, [%4];" \
                 : "=r"(r0), "=r"(r1), "=r"(r2), "=r"(r3) : "r"(addr))

#define MMA_16816(c, a, b0, b1) \
    asm volatile("mma.sync.aligned.m16n8k16.row.col.f32.bf16.bf16.f32 " \
                 "{%0,%1,%2,%3}, {%4,%5,%6,%7}, {%8,%9}, {%0,%1,%2,%3};" \
                 : "+f"((c)[0]), "+f"((c)[1]), "+f"((c)[2]), "+f"((c)[3]) \
                 : "r"((a)[0]), "r"((a)[1]), "r"((a)[2]), "r"((a)[3]), \
                   "r"(b0), "r"(b1))

#define BAR_SYNC(id, cnt)   asm volatile("bar.sync %0, %1;"   :: "r"(id), "r"(cnt) : "memory")
#define BAR_ARRIVE(id, cnt) asm volatile("bar.arrive %0, %1;" :: "r"(id), "r"(cnt) : "memory")

// Swizzled byte offset inside a row-major operand (256 B/row, 16B chunks
// XOR-swizzled by row&7).
__device__ __forceinline__ uint32_t sw_off(int row, int kbyte) {
    int c = kbyte >> 4;
    return (uint32_t)(row * 256 + (((c ^ (row & 7)) << 4) | (kbyte & 15)));
}

// ---------------------------------------------------------------------------
// Stage 1: A, B (b1 folded), W2 -> bf16 hi/lo in swizzled [n][k] layout
// ---------------------------------------------------------------------------
__global__ void precompute_kernel(const float* __restrict__ z1,
                                  const float* __restrict__ z2,
                                  const float* __restrict__ W1,
                                  const float* __restrict__ b1,
                                  const float* __restrict__ W2) {
    int row = blockIdx.x;
    int h = threadIdx.x;  // 128 threads
    if (row < 2 * NPTS) {
        __shared__ float zsh[EMB];
        const float* z = (row < NPTS) ? (z1 + (size_t)row * EMB)
                                      : (z2 + (size_t)(row - NPTS) * EMB);
        zsh[h] = z[h];
        __syncthreads();
        const float* w = (row < NPTS) ? (W1 + (size_t)h * (2 * EMB))
                                      : (W1 + (size_t)h * (2 * EMB) + EMB);
        float s = 0.f;
#pragma unroll 8
        for (int d = 0; d < EMB; ++d) s += zsh[d] * w[d];
        if (row < NPTS) g_A[(size_t)row * HID + h] = s;
        else            g_B[(size_t)(row - NPTS) * HID + h] = s + b1[h];
    } else {
        int g = row - 2 * NPTS;   // n index 0..127
        float w = W2[(size_t)g * HID + h];
        __nv_bfloat16 hi = __float2bfloat16(w);
        __nv_bfloat16 lo = __float2bfloat16(w - __bfloat162float(hi));
        uint32_t off = sw_off(g, 2 * h) >> 1;
        g_W2hi[off] = __bfloat16_as_ushort(hi);
        g_W2lo[off] = __bfloat16_as_ushort(lo);
    }
}

// ---------------------------------------------------------------------------
// SMEM layout (byte offsets)
// ---------------------------------------------------------------------------
#define OFF_WHI 0
#define OFF_WLO 32768
#define OFF_H1  65536                       // NBUF bufs x (hi 16384 + lo 16384)
#define OFF_A   (OFF_H1 + NBUF * 32768)     // 8*128 floats (4 KB)
#define OFF_B   (OFF_A + 4096)              // 8*128 floats (4 KB)
#define OFF_B2  (OFF_B + 4096)
#define OFF_W3  (OFF_B2 + 512)
#define OFF_RED (OFF_W3 + 512)              // 64*3 floats
#define SMEM_TOTAL (OFF_RED + 64 * 3 * 4 + 128)

// barrier ids: full = 1+buf, empty = 5+buf, producer-internal = 9, reduce = 10

// ---------------------------------------------------------------------------
// Persistent warp-specialized kernel
// ---------------------------------------------------------------------------
__global__ __launch_bounds__(THREADS, 1)
void pair_mlp_ws(const float* __restrict__ b2,
                 const float* __restrict__ W3,
                 const float* __restrict__ b3,
                 float* __restrict__ out) {
    extern __shared__ char smem[];
    const uint32_t sb = smem_u32(smem);
    const int tid  = threadIdx.x;
    const int lane = tid & 31;

    float* sA   = reinterpret_cast<float*>(smem + OFF_A);
    float* sB   = reinterpret_cast<float*>(smem + OFF_B);
    float* sb2  = reinterpret_cast<float*>(smem + OFF_B2);
    float* sw3  = reinterpret_cast<float*>(smem + OFF_W3);
    float* sRed = reinterpret_cast<float*>(smem + OFF_RED);

    // one-time: stage W2 hi/lo (pre-swizzled), b2, w3
    {
        const uint4* shi = reinterpret_cast<const uint4*>(g_W2hi);
        const uint4* slo = reinterpret_cast<const uint4*>(g_W2lo);
        uint4* dh = reinterpret_cast<uint4*>(smem + OFF_WHI);
        uint4* dl = reinterpret_cast<uint4*>(smem + OFF_WLO);
        for (int k = tid; k < 2048; k += THREADS) { dh[k] = shi[k]; dl[k] = slo[k]; }
        if (tid < 128) { sb2[tid] = b2[tid]; sw3[tid] = W3[tid]; }
    }
    const float b3v = b3[0];
    __syncthreads();

    if (tid < 256) {
        // ================= CONSUMER: warps 0-7, warp tile 16(m) x 64(n) ======
        const int wid = tid >> 5;
        const int wm = wid & 3, wn = wid >> 2;
        const int Mbase = wm * 16, Nbase = wn * 64;
        const int arow0 = Mbase + (lane & 15);
        const int aKhi  = lane >> 4;
        const int fA    = arow0 & 7;
        const int bn0   = ((lane >> 4) << 3) + (lane & 7);
        const int bKhi  = (lane >> 3) & 1;
        const int fB    = bn0 & 7;

        int nt = 0;
        for (int t = blockIdx.x; t < NTILES; t += gridDim.x, ++nt) {
            const int buf = nt & (NBUF - 1);
            BAR_SYNC(1 + buf, 512);                 // wait full

            const uint32_t hbase = sb + OFF_H1 + buf * 32768;
            const uint32_t lbase = hbase + 16384;

            float acc[8][4];
#pragma unroll
            for (int q = 0; q < 8; ++q)
#pragma unroll
                for (int r = 0; r < 4; ++r) acc[q][r] = 0.f;

#pragma unroll
            for (int ks = 0; ks < 8; ++ks) {
                const int cA = 2 * ks + aKhi;
                const int cB = 2 * ks + bKhi;
                uint32_t ahi[4], alo[4];
                const uint32_t offA = (uint32_t)(arow0 * 256 + ((cA ^ fA) << 4));
                LDSM_X4(ahi[0], ahi[1], ahi[2], ahi[3], hbase + offA);
                LDSM_X4(alo[0], alo[1], alo[2], alo[3], lbase + offA);
#pragma unroll
                for (int nh = 0; nh < 2; ++nh) {
                    uint32_t bhi[2][4], blo[2][4];
#pragma unroll
                    for (int p = 0; p < 2; ++p) {
                        const int row = Nbase + nh * 32 + p * 16 + bn0;
                        const uint32_t offB = (uint32_t)(row * 256 + ((cB ^ fB) << 4));
                        LDSM_X4(bhi[p][0], bhi[p][1], bhi[p][2], bhi[p][3], sb + OFF_WHI + offB);
                        LDSM_X4(blo[p][0], blo[p][1], blo[p][2], blo[p][3], sb + OFF_WLO + offB);
                    }
#pragma unroll
                    for (int q = 0; q < 4; ++q) {
                        const int p = q >> 1, o = (q & 1) * 2;
                        float* c = acc[nh * 4 + q];
                        MMA_16816(c, ahi, bhi[p][o], bhi[p][o + 1]);
                        MMA_16816(c, ahi, blo[p][o], blo[p][o + 1]);
                        MMA_16816(c, alo, bhi[p][o], bhi[p][o + 1]);
                    }
                }
            }

            // epilogue: gelu(acc+b2)*w3, reduce over n
            float part[2] = {0.f, 0.f};
#pragma unroll
            for (int q = 0; q < 8; ++q)
#pragma unroll
                for (int r = 0; r < 4; ++r) {
                    const int n = Nbase + q * 8 + ((lane & 3) << 1) + (r & 1);
                    part[r >> 1] += gelu_exact(acc[q][r] + sb2[n]) * sw3[n];
                }
#pragma unroll
            for (int hh = 0; hh < 2; ++hh) {
                float v = part[hh];
                v += __shfl_xor_sync(0xFFFFFFFFu, v, 1);
                v += __shfl_xor_sync(0xFFFFFFFFu, v, 2);
                part[hh] = v;
            }
            if ((lane & 3) == 0) {
#pragma unroll
                for (int hh = 0; hh < 2; ++hh) {
                    const int m = Mbase + hh * 8 + (lane >> 2);
                    sRed[m * 3 + wn] = part[hh];
                }
            }
            BAR_SYNC(10, 256);
            if (tid < 64) {
                const float s = b3v + sRed[tid * 3 + 0] + sRed[tid * 3 + 1];
                const int i0 = (t >> 7) * TI, j0 = (t & 127) * TJ;
                out[(size_t)(i0 + (tid >> 3)) * NPTS + (j0 + (tid & 7))] = s;
            }
            BAR_SYNC(10, 256);                      // protect sRed reuse
            BAR_ARRIVE(5 + buf, 512);               // signal empty
        }
    } else {
        // ================= PRODUCER: warps 8-15, fill h1 hi/lo ===============
        const int ptid = tid - 256;
        const int pwid = ptid >> 5;

        int nt = 0;
        for (int t = blockIdx.x; t < NTILES; t += gridDim.x, ++nt) {
            const int buf = nt & (NBUF - 1);
            if (nt >= NBUF) BAR_SYNC(5 + buf, 512); // wait empty

            const int i0 = (t >> 7) * TI, j0 = (t & 127) * TJ;
            reinterpret_cast<float4*>(sA)[ptid] =
                reinterpret_cast<const float4*>(g_A + (size_t)j0 * HID)[ptid];
            reinterpret_cast<float4*>(sB)[ptid] =
                reinterpret_cast<const float4*>(g_B + (size_t)i0 * HID)[ptid];
            BAR_SYNC(9, 256);                       // staging -> fill

            char* basehi = smem + OFF_H1 + buf * 32768;
            char* baselo = basehi + 16384;
#pragma unroll
            for (int r = 0; r < 8; ++r) {
                const int m  = pwid * 8 + r;
                const int jj = m & 7, ii = m >> 3;
                float4 av = reinterpret_cast<const float4*>(sA + jj * HID)[lane];
                float4 bv = reinterpret_cast<const float4*>(sB + ii * HID)[lane];
                float y0 = gelu_exact(av.x + bv.x);
                float y1 = gelu_exact(av.y + bv.y);
                float y2 = gelu_exact(av.z + bv.z);
                float y3 = gelu_exact(av.w + bv.w);
                uint32_t hp0, hp1, lp0, lp1;
                asm("cvt.rn.bf16x2.f32 %0, %1, %2;" : "=r"(hp0) : "f"(y1), "f"(y0));
                asm("cvt.rn.bf16x2.f32 %0, %1, %2;" : "=r"(hp1) : "f"(y3), "f"(y2));
                float l0 = y0 - __uint_as_float(hp0 << 16);
                float l1 = y1 - __uint_as_float(hp0 & 0xFFFF0000u);
                float l2 = y2 - __uint_as_float(hp1 << 16);
                float l3 = y3 - __uint_as_float(hp1 & 0xFFFF0000u);
                asm("cvt.rn.bf16x2.f32 %0, %1, %2;" : "=r"(lp0) : "f"(l1), "f"(l0));
                asm("cvt.rn.bf16x2.f32 %0, %1, %2;" : "=r"(lp1) : "f"(l3), "f"(l2));
                const uint32_t o = sw_off(m, 8 * lane);
                *reinterpret_cast<uint2*>(basehi + o) = make_uint2(hp0, hp1);
                *reinterpret_cast<uint2*>(baselo + o) = make_uint2(lp0, lp1);
            }
            BAR_ARRIVE(1 + buf, 512);               // signal full
            BAR_SYNC(9, 256);                       // protect sA/sB reuse
        }
    }
}

// ---------------------------------------------------------------------------
extern "C" void kernel_launch(void* const* d_in, const int* in_sizes, int n_in,
                              void* d_out, int out_size) {
    const float* z1 = (const float*)d_in[0];
    const float* z2 = (const float*)d_in[1];
    const float* W1 = (const float*)d_in[2];
    const float* b1 = (const float*)d_in[3];
    const float* W2 = (const float*)d_in[4];
    const float* b2 = (const float*)d_in[5];
    const float* W3 = (const float*)d_in[6];
    const float* b3 = (const float*)d_in[7];
    float* out = (float*)d_out;
    (void)in_sizes; (void)n_in; (void)out_size;

    precompute_kernel<<<2 * NPTS + HID, 128>>>(z1, z2, W1, b1, W2);

    int sm_count = 0;
    cudaDeviceGetAttribute(&sm_count, cudaDevAttrMultiProcessorCount, 0);
    cudaFuncSetAttribute(pair_mlp_ws,
                         cudaFuncAttributeMaxDynamicSharedMemorySize, SMEM_TOTAL);
    pair_mlp_ws<<<sm_count, THREADS, SMEM_TOTAL>>>(b2, W3, b3, out);
}